// round 13
// baseline (speedup 1.0000x reference)
#include <cuda_runtime.h>
#include <cuda_bf16.h>
#include <mma.h>
#include <math.h>
#include <cstdint>

using namespace nvcuda;

// Problem constants
#define NN 50000
#define NE 800000
#define F  128
#define R  8
#define NKEY (NN * R)                // 400000 (rel,dst) buckets, key = rel*NN + dst

// smem tile row: 136 bf16 = 272 bytes -> LDSM rows hit banks 4r mod 32 (conflict-free)
#define PADC 136
#define ROW2W 34                     // uint2 per padded weight row
#define ROWB (PADC * 2)              // 272 bytes
#define TILEA (64 * ROWB)            // 17408: 64-row A tile
#define TILEW (128 * ROWB)           // 34816: 128-row B (weight) tile
#define STAGEB (TILEA + TILEW)       // 52224 per stage
#define GEMM_SMEM (2 * STAGEB + 64)  // 2 stages + mbarriers = 104512 -> 2 CTAs/SM

#define MROWS 64                     // rows per CTA
#define GRID ((NN + MROWS - 1) / MROWS)   // 782

// ---------------- device scratch (no cudaMalloc allowed) ----------------
__device__ __nv_bfloat16 g_h1[(size_t)NN * F];
__device__ __nv_bfloat16 g_hbf[(size_t)NN * F];
__device__ __nv_bfloat16 g_Wb1[9 * 128 * PADC];   // W1 blocks (+self), padded rows
__device__ __nv_bfloat16 g_Wb2[9 * 128 * PADC];
__device__ int      g_deg2[NKEY];
__device__ int      g_off2[NKEY + 1];
__device__ int      g_cur2[NKEY];
__device__ int      g_bsum[128];
__device__ int      g_boff[128];
__device__ int      g_tick;
__device__ volatile int g_flag;
__device__ uint32_t g_epack[NE];                  // src | dst<<16, sorted by (rel,dst)
__device__ float    g_pool[F];

// ---------------- PTX helpers ----------------
__device__ __forceinline__ void mbar_init(uint32_t mbar, uint32_t cnt) {
    asm volatile("mbarrier.init.shared.b64 [%0], %1;" :: "r"(mbar), "r"(cnt) : "memory");
}
__device__ __forceinline__ void mbar_arrive(uint32_t mbar) {
    asm volatile("mbarrier.arrive.release.cta.shared::cta.b64 _, [%0];" :: "r"(mbar) : "memory");
}
__device__ __forceinline__ void mbar_arrive_expect_tx(uint32_t mbar, uint32_t bytes) {
    asm volatile("mbarrier.arrive.expect_tx.shared.b64 _, [%0], %1;"
                 :: "r"(mbar), "r"(bytes) : "memory");
}
__device__ __forceinline__ void mbar_wait(uint32_t mbar, uint32_t parity) {
    asm volatile(
        "{\n\t.reg .pred P;\n\t"
        "W%=:\n\t"
        "mbarrier.try_wait.parity.acquire.cta.shared::cta.b64 P, [%0], %1, 0x989680;\n\t"
        "@!P bra.uni W%=;\n\t}"
        :: "r"(mbar), "r"(parity) : "memory");
}
__device__ __forceinline__ void bulk_g2s(uint32_t sdst, const void* gsrc, uint32_t bytes,
                                         uint32_t mbar) {
    asm volatile(
        "cp.async.bulk.shared::cta.global.mbarrier::complete_tx::bytes [%0], [%1], %2, [%3];"
        :: "r"(sdst), "l"(gsrc), "r"(bytes), "r"(mbar) : "memory");
}

// ---------------- launch 1: hist + all fp32->bf16 converts ----------------
#define NH_BLK ((NE + 255) / 256)
#define NC_BLK ((NN * F / 4 + 255) / 256)
#define NW_ELEM (9 * F * F / 4)
#define NW_BLK ((NW_ELEM + 255) / 256)
#define FRONT_GRID (NH_BLK + NC_BLK + 2 * NW_BLK)

__global__ void __launch_bounds__(256)
k_front(const float* __restrict__ in_feat,
        const float* __restrict__ W1, const float* __restrict__ W1s,
        const float* __restrict__ W2, const float* __restrict__ W2s,
        const int* __restrict__ dst, const int* __restrict__ et) {
    int b = blockIdx.x;
    int t = threadIdx.x;
    if (b < NH_BLK) {
        int e = b * 256 + t;
        if (e < NE) atomicAdd(&g_deg2[et[e] * NN + dst[e]], 1);
        return;
    }
    b -= NH_BLK;
    if (b < NC_BLK) {
        int i = b * 256 + t;
        if (i >= NN * F / 4) return;
        float4 v = ((const float4*)in_feat)[i];
        __nv_bfloat162 p0 = __floats2bfloat162_rn(v.x, v.y);
        __nv_bfloat162 p1 = __floats2bfloat162_rn(v.z, v.w);
        uint2 o; o.x = *(unsigned*)&p0; o.y = *(unsigned*)&p1;
        ((uint2*)g_hbf)[i] = o;
        return;
    }
    b -= NC_BLK;
    int which = (b < NW_BLK) ? 0 : 1;
    if (which) b -= NW_BLK;
    int i = b * 256 + t;
    if (i >= NW_ELEM) return;
    const float* W  = which ? W2  : W1;
    const float* Ws = which ? W2s : W1s;
    const float4* src = (i < 8 * F * F / 4) ? ((const float4*)W + i)
                                            : ((const float4*)Ws + (i - 8 * F * F / 4));
    float4 v = *src;
    __nv_bfloat162 p0 = __floats2bfloat162_rn(v.x, v.y);
    __nv_bfloat162 p1 = __floats2bfloat162_rn(v.z, v.w);
    uint2 o; o.x = *(unsigned*)&p0; o.y = *(unsigned*)&p1;
    int row = i >> 5, c4 = i & 31;
    ((uint2*)(which == 0 ? g_Wb1 : g_Wb2))[(size_t)row * ROW2W + c4] = o;
}

// ---------------- launch 2: single-kernel scan (fence-and-flag, 98 resident blocks) ----------------
#define SCAN_BLK 98

__global__ void __launch_bounds__(1024) k_scan() {
    __shared__ int ws[32];
    __shared__ int s_last;
    int b = blockIdx.x, t = threadIdx.x;
    int lane = t & 31, wid = t >> 5;
    int base = b * 4096 + t * 4;
    int4 v4 = make_int4(0, 0, 0, 0);
    if (base + 3 < NKEY) v4 = *(const int4*)&g_deg2[base];
    else if (base < NKEY) {
        v4.x = g_deg2[base];
        if (base + 1 < NKEY) v4.y = g_deg2[base + 1];
        if (base + 2 < NKEY) v4.z = g_deg2[base + 2];
    }
    int s = v4.x + v4.y + v4.z + v4.w;
    int x = s;
    #pragma unroll
    for (int o = 1; o < 32; o <<= 1) { int u = __shfl_up_sync(~0u, x, o); if (lane >= o) x += u; }
    if (lane == 31) ws[wid] = x;
    __syncthreads();
    if (wid == 0) {
        int w = ws[lane];
        #pragma unroll
        for (int o = 1; o < 32; o <<= 1) { int u = __shfl_up_sync(~0u, w, o); if (lane >= o) w += u; }
        ws[lane] = w;
    }
    __syncthreads();
    int blk_excl = (x - s) + (wid > 0 ? ws[wid - 1] : 0);
    int blk_total = ws[31];
    __syncthreads();
    if (t == 0) {
        g_bsum[b] = blk_total;
        __threadfence();
        int tk = atomicAdd(&g_tick, 1);
        s_last = (tk == SCAN_BLK - 1) ? 1 : 0;
    }
    __syncthreads();
    if (s_last && wid == 0) {
        int v[4]; int psum = 0;
        #pragma unroll
        for (int j = 0; j < 4; j++) {
            int k = lane * 4 + j;
            v[j] = (k < SCAN_BLK) ? g_bsum[k] : 0;
            psum += v[j];
        }
        int xx = psum;
        #pragma unroll
        for (int o = 1; o < 32; o <<= 1) { int u = __shfl_up_sync(~0u, xx, o); if (lane >= o) xx += u; }
        int run = xx - psum;
        #pragma unroll
        for (int j = 0; j < 4; j++) {
            int k = lane * 4 + j;
            if (k < SCAN_BLK) g_boff[k] = run;
            run += v[j];
        }
        if (lane == 31) g_off2[NKEY] = run;
        __syncwarp();
        if (lane == 0) { __threadfence(); g_flag = 1; }
    }
    if (t == 0) { while (g_flag == 0) __nanosleep(64); }
    __syncthreads();
    __threadfence();
    int bb = g_boff[b] + blk_excl;
    int e0 = bb;
    int e1 = e0 + v4.x;
    int e2 = e1 + v4.y;
    int e3 = e2 + v4.z;
    if (base + 3 < NKEY) {
        *(int4*)&g_off2[base] = make_int4(e0, e1, e2, e3);
        *(int4*)&g_cur2[base] = make_int4(e0, e1, e2, e3);
    } else if (base < NKEY) {
        g_off2[base] = e0; g_cur2[base] = e0;
        if (base + 1 < NKEY) { g_off2[base + 1] = e1; g_cur2[base + 1] = e1; }
        if (base + 2 < NKEY) { g_off2[base + 2] = e2; g_cur2[base + 2] = e2; }
    }
}

// ---------------- launch 3: scatter (+ reset scan flags) ----------------
__global__ void k_scatter(const int* __restrict__ src, const int* __restrict__ dst,
                          const int* __restrict__ et) {
    if (blockIdx.x == 0 && threadIdx.x == 0) { g_tick = 0; g_flag = 0; }
    int e = blockIdx.x * blockDim.x + threadIdx.x;
    if (e < NE) {
        int d = dst[e];
        int p = atomicAdd(&g_cur2[et[e] * NN + d], 1);
        g_epack[p] = (uint32_t)src[e] | ((uint32_t)d << 16);
    }
}

// ---------------- launch 4/5: fused gather + GEMM + epilogue ----------------
// 64-row CTA, 256 threads: warps 0-3 consumers (wmma), warps 4-7 producers (gather).
// 104.5KB smem -> 2 CTAs/SM: two independent pipelines hide each other's stalls.
__global__ void __launch_bounds__(256)
k_fused(const float* __restrict__ bias, int layer) {
    extern __shared__ char smraw[];
    uint32_t sbase = (uint32_t)__cvta_generic_to_shared(smraw);
    const __nv_bfloat16* hinp = layer ? g_h1 : g_hbf;
    const uint2* hin4 = (const uint2*)hinp;       // dense: 32 uint2 per row
    const __nv_bfloat16* Wb = layer ? g_Wb2 : g_Wb1;
    int m0 = blockIdx.x * MROWS;
    int t = threadIdx.x;
    int warp = t >> 5, lane = t & 31;
    uint32_t mbF0 = sbase + 2 * STAGEB;           // full[0], full[1]
    uint32_t mbE0 = mbF0 + 16;                    // empty[0], empty[1]

    if (t == 0) {
        mbar_init(mbF0, 129);     mbar_init(mbF0 + 8, 129);   // 128 producer thr + expect_tx
        mbar_init(mbE0, 128);     mbar_init(mbE0 + 8, 128);   // 128 consumer thr
    }
    __syncthreads();

    if (warp < 4) {
        // ---------------- consumer: warp tile 32x64 ----------------
        int wm = warp >> 1;      // 0..1 (32-row tiles)
        int wn = warp & 1;       // 0..1 (64-col tiles)
        wmma::fragment<wmma::accumulator, 16, 16, 16, float> c[2][4];
        #pragma unroll
        for (int i = 0; i < 2; i++)
            #pragma unroll
            for (int j = 0; j < 4; j++) wmma::fill_fragment(c[i][j], 0.f);

        for (int kb = 0; kb < 9; kb++) {
            int s = kb & 1;
            uint32_t par = (kb >> 1) & 1;
            mbar_wait(mbF0 + 8 * s, par);
            const __nv_bfloat16* sA = (const __nv_bfloat16*)(smraw + s * STAGEB);
            const __nv_bfloat16* sB = (const __nv_bfloat16*)(smraw + s * STAGEB + TILEA);
            #pragma unroll
            for (int ks = 0; ks < 8; ks++) {
                wmma::fragment<wmma::matrix_b, 16, 16, 16, __nv_bfloat16, wmma::row_major> bf[4];
                #pragma unroll
                for (int j = 0; j < 4; j++)
                    wmma::load_matrix_sync(bf[j], sB + (ks * 16) * PADC + wn * 64 + j * 16, PADC);
                #pragma unroll
                for (int i = 0; i < 2; i++) {
                    wmma::fragment<wmma::matrix_a, 16, 16, 16, __nv_bfloat16, wmma::row_major> af;
                    wmma::load_matrix_sync(af, sA + (wm * 32 + i * 16) * PADC + ks * 16, PADC);
                    #pragma unroll
                    for (int j = 0; j < 4; j++)
                        wmma::mma_sync(c[i][j], af, bf[j], c[i][j]);
                }
            }
            mbar_arrive(mbE0 + 8 * s);
        }
        __syncthreads();
        float* sC = (float*)smraw;
        #pragma unroll
        for (int i = 0; i < 2; i++)
            #pragma unroll
            for (int j = 0; j < 4; j++)
                wmma::store_matrix_sync(sC + (wm * 32 + i * 16) * 132 + wn * 64 + j * 16,
                                        c[i][j], 132, wmma::mem_row_major);
    } else {
        // ---------------- producer ----------------
        int pw = warp - 4;                        // 0..3, owns rows pw*16..pw*16+15
        int nn = NN - m0; if (nn > MROWS) nn = MROWS;
        for (int kb = 0; kb < 9; kb++) {
            int s = kb & 1;
            uint32_t par = ((kb >> 1) & 1) ^ 1;
            mbar_wait(mbE0 + 8 * s, par);
            uint32_t mbF = mbF0 + 8 * s;
            char* sAp = smraw + s * STAGEB;
            if (t == 128) {
                mbar_arrive_expect_tx(mbF, TILEW);
                bulk_g2s(sbase + s * STAGEB + TILEA,
                         (const void*)(Wb + (size_t)kb * 128 * PADC), TILEW, mbF);
            }
            if (kb < 8) {
                #pragma unroll
                for (int r = 0; r < 16; r++)
                    *(uint2*)(sAp + (pw * 16 + r) * ROWB + lane * 8) = make_uint2(0u, 0u);
                int nbeg = pw * 16;
                int nend = nbeg + 16; if (nend > nn) nend = nn;
                if (nbeg < nend) {
                    int wb = g_off2[kb * NN + m0 + nbeg];
                    int we = g_off2[kb * NN + m0 + nend];
                    int cur = -1;
                    float a0 = 0.f, a1 = 0.f, a2 = 0.f, a3 = 0.f;
                    for (int e = wb; e < we; e += 32) {
                        uint32_t pk = 0xFFFF0000u;               // sentinel dst
                        if (e + lane < we) pk = g_epack[e + lane];
                        int ccnt = we - e; if (ccnt > 32) ccnt = 32;
                        for (int g = 0; g < ccnt; g += 8) {
                            uint2 rr[8]; int dd[8];
                            #pragma unroll
                            for (int j = 0; j < 8; j++) {
                                uint32_t p = __shfl_sync(0xffffffffu, pk, g + j);
                                dd[j] = (int)(p >> 16);
                                rr[j] = hin4[(size_t)(p & 0xFFFFu) * 32 + lane];
                            }
                            #pragma unroll
                            for (int j = 0; j < 8; j++) {
                                if (dd[j] == 0xFFFF) continue;
                                if (dd[j] != cur) {
                                    if (cur >= 0) {
                                        __nv_bfloat162 o0 = __floats2bfloat162_rn(a0, a1);
                                        __nv_bfloat162 o1 = __floats2bfloat162_rn(a2, a3);
                                        *(uint2*)(sAp + (cur - m0) * ROWB + lane * 8) =
                                            make_uint2(*(unsigned*)&o0, *(unsigned*)&o1);
                                    }
                                    cur = dd[j];
                                    a0 = a1 = a2 = a3 = 0.f;
                                }
                                __nv_bfloat162 p0 = *(__nv_bfloat162*)&rr[j].x;
                                __nv_bfloat162 p1 = *(__nv_bfloat162*)&rr[j].y;
                                float2 f0 = __bfloat1622float2(p0);
                                float2 f1 = __bfloat1622float2(p1);
                                a0 += f0.x; a1 += f0.y; a2 += f1.x; a3 += f1.y;
                            }
                        }
                    }
                    if (cur >= 0) {
                        __nv_bfloat162 o0 = __floats2bfloat162_rn(a0, a1);
                        __nv_bfloat162 o1 = __floats2bfloat162_rn(a2, a3);
                        *(uint2*)(sAp + (cur - m0) * ROWB + lane * 8) =
                            make_uint2(*(unsigned*)&o0, *(unsigned*)&o1);
                    }
                }
            } else {
                // self-loop stage: copy my 16 h rows into sA
                #pragma unroll
                for (int r = 0; r < 16; r++) {
                    int row = pw * 16 + r;
                    int gr = m0 + row;
                    uint2 v = (gr < NN) ? hin4[(size_t)gr * 32 + lane] : make_uint2(0u, 0u);
                    *(uint2*)(sAp + row * ROWB + lane * 8) = v;
                }
            }
            mbar_arrive(mbF);
        }
        __syncthreads();
    }
    __syncthreads();

    // ---------------- epilogue (all 256 threads), C is 64x132 fp32 ----------------
    float* sC = (float*)smraw;
    if (layer == 0) {
        #pragma unroll
        for (int i = 0; i < 8; i++) {
            int idx = t + i * 256;               // 0..2047
            int row = idx >> 5;
            int c4  = idx & 31;
            if (m0 + row < NN) {
                float* sp = sC + row * 132 + c4 * 4;
                float x = fmaxf(sp[0] + bias[c4 * 4 + 0], 0.f);
                float y = fmaxf(sp[1] + bias[c4 * 4 + 1], 0.f);
                float z = fmaxf(sp[2] + bias[c4 * 4 + 2], 0.f);
                float w = fmaxf(sp[3] + bias[c4 * 4 + 3], 0.f);
                __nv_bfloat162 p0 = __floats2bfloat162_rn(x, y);
                __nv_bfloat162 p1 = __floats2bfloat162_rn(z, w);
                uint2 o; o.x = *(unsigned*)&p0; o.y = *(unsigned*)&p1;
                ((uint2*)g_h1)[(size_t)(m0 + row) * 32 + c4] = o;
            }
        }
    } else {
        int col = t & 127;
        int rg = t >> 7;                         // 0..1
        float bc = bias[col];
        float s = 0.f;
        for (int r = rg * 32; r < rg * 32 + 32; r++) {
            if (m0 + r < NN) s += fmaxf(sC[r * 132 + col] + bc, 0.f);
        }
        atomicAdd(&g_pool[col], s);
        // re-zero g_deg2 for the next replay
        int gid = blockIdx.x * 256 + t;
        if (gid < NKEY / 2) ((int2*)g_deg2)[gid] = make_int2(0, 0);
    }
}

// ---------------- launch 6: final (+ re-zero pool) ----------------
__global__ void k_final(const float* __restrict__ fc_w, const float* __restrict__ fc_b,
                        float* __restrict__ out) {
    __shared__ float red[F];
    int t = threadIdx.x;
    red[t] = g_pool[t] * (1.f / (float)NN) * fc_w[t];
    __syncthreads();
    for (int o = 64; o > 0; o >>= 1) {
        if (t < o) red[t] += red[t + o];
        __syncthreads();
    }
    if (t == 0) {
        float logit = red[0] + fc_b[0];
        out[0] = 1.f / (1.f + expf(-logit));
    }
    g_pool[t] = 0.f;
}

// ---------------- launch ----------------
extern "C" void kernel_launch(void* const* d_in, const int* in_sizes, int n_in,
                              void* d_out, int out_size) {
    const float* in_feat = (const float*)d_in[0];
    const float* W1   = (const float*)d_in[1];
    const float* W1s  = (const float*)d_in[2];
    const float* b1   = (const float*)d_in[3];
    const float* W2   = (const float*)d_in[4];
    const float* W2s  = (const float*)d_in[5];
    const float* b2   = (const float*)d_in[6];
    const float* fcw  = (const float*)d_in[7];
    const float* fcb  = (const float*)d_in[8];
    const int*   src  = (const int*)d_in[9];
    const int*   dst  = (const int*)d_in[10];
    const int*   et   = (const int*)d_in[11];
    float* out = (float*)d_out;

    cudaFuncSetAttribute(k_fused, cudaFuncAttributeMaxDynamicSharedMemorySize, GEMM_SMEM);

    k_front<<<FRONT_GRID, 256>>>(in_feat, W1, W1s, W2, W2s, dst, et);   // 1
    k_scan<<<SCAN_BLK, 1024>>>();                                       // 2
    k_scatter<<<(NE + 255) / 256, 256>>>(src, dst, et);                 // 3
    k_fused<<<GRID, 256, GEMM_SMEM>>>(b1, 0);                           // 4  <- ncu target
    k_fused<<<GRID, 256, GEMM_SMEM>>>(b2, 1);                           // 5
    k_final<<<1, 128>>>(fcw, fcb, out);                                 // 6
}

// round 14
// speedup vs baseline: 1.3930x; 1.3930x over previous
#include <cuda_runtime.h>
#include <cuda_bf16.h>
#include <mma.h>
#include <math.h>
#include <cstdint>

using namespace nvcuda;

// Problem constants
#define NN 50000
#define NE 800000
#define F  128
#define R  8
#define NKEY (NN * R)                // 400000 (rel,dst) buckets, key = rel*NN + dst

// smem tile row: 136 bf16 = 272 bytes -> LDSM rows hit banks 4r mod 32 (conflict-free)
#define PADC 136
#define ROW2W 34                     // uint2 per padded weight row
#define ROWB (PADC * 2)              // 272 bytes
#define TILEA (64 * ROWB)            // 17408: 64-row A tile
#define TILEW (128 * ROWB)           // 34816: 128-row B (weight) tile
#define STAGEB (TILEA + TILEW)       // 52224 per stage
#define GEMM_SMEM (2 * STAGEB + 64)  // 2 stages + mbarriers = 104512 -> 2 CTAs/SM

#define MROWS 64                     // rows per CTA
#define GRID ((NN + MROWS - 1) / MROWS)   // 782

// ---------------- device scratch (no cudaMalloc allowed) ----------------
__device__ __nv_bfloat16 g_h1[(size_t)NN * F];
__device__ __nv_bfloat16 g_hbf[(size_t)NN * F];
__device__ __nv_bfloat16 g_Wb1[9 * 128 * PADC];   // W1 blocks (+self), padded rows
__device__ __nv_bfloat16 g_Wb2[9 * 128 * PADC];
__device__ int      g_deg2[NKEY];
__device__ int      g_off2[NKEY + 1];
__device__ int      g_cur2[NKEY];
__device__ int      g_bsum[128];
__device__ int      g_boff[128];
__device__ int      g_tick;
__device__ volatile int g_flag;
__device__ uint32_t g_epack[NE];                  // src | dst<<16, sorted by (rel,dst)
__device__ float    g_pool[F];

// ---------------- PTX helpers ----------------
__device__ __forceinline__ void mbar_init(uint32_t mbar, uint32_t cnt) {
    asm volatile("mbarrier.init.shared.b64 [%0], %1;" :: "r"(mbar), "r"(cnt) : "memory");
}
__device__ __forceinline__ void mbar_arrive(uint32_t mbar) {
    asm volatile("mbarrier.arrive.release.cta.shared::cta.b64 _, [%0];" :: "r"(mbar) : "memory");
}
__device__ __forceinline__ void mbar_arrive_expect_tx(uint32_t mbar, uint32_t bytes) {
    asm volatile("mbarrier.arrive.expect_tx.shared.b64 _, [%0], %1;"
                 :: "r"(mbar), "r"(bytes) : "memory");
}
__device__ __forceinline__ void mbar_wait(uint32_t mbar, uint32_t parity) {
    asm volatile(
        "{\n\t.reg .pred P;\n\t"
        "W%=:\n\t"
        "mbarrier.try_wait.parity.acquire.cta.shared::cta.b64 P, [%0], %1, 0x989680;\n\t"
        "@!P bra.uni W%=;\n\t}"
        :: "r"(mbar), "r"(parity) : "memory");
}
__device__ __forceinline__ void bulk_g2s(uint32_t sdst, const void* gsrc, uint32_t bytes,
                                         uint32_t mbar) {
    asm volatile(
        "cp.async.bulk.shared::cta.global.mbarrier::complete_tx::bytes [%0], [%1], %2, [%3];"
        :: "r"(sdst), "l"(gsrc), "r"(bytes), "r"(mbar) : "memory");
}

// ---------------- launch 1: hist + all fp32->bf16 converts ----------------
#define NH_BLK ((NE + 255) / 256)
#define NC_BLK ((NN * F / 4 + 255) / 256)
#define NW_ELEM (9 * F * F / 4)
#define NW_BLK ((NW_ELEM + 255) / 256)
#define FRONT_GRID (NH_BLK + NC_BLK + 2 * NW_BLK)

__global__ void __launch_bounds__(256)
k_front(const float* __restrict__ in_feat,
        const float* __restrict__ W1, const float* __restrict__ W1s,
        const float* __restrict__ W2, const float* __restrict__ W2s,
        const int* __restrict__ dst, const int* __restrict__ et) {
    int b = blockIdx.x;
    int t = threadIdx.x;
    if (b < NH_BLK) {
        int e = b * 256 + t;
        if (e < NE) atomicAdd(&g_deg2[et[e] * NN + dst[e]], 1);
        return;
    }
    b -= NH_BLK;
    if (b < NC_BLK) {
        int i = b * 256 + t;
        if (i >= NN * F / 4) return;
        float4 v = ((const float4*)in_feat)[i];
        __nv_bfloat162 p0 = __floats2bfloat162_rn(v.x, v.y);
        __nv_bfloat162 p1 = __floats2bfloat162_rn(v.z, v.w);
        uint2 o; o.x = *(unsigned*)&p0; o.y = *(unsigned*)&p1;
        ((uint2*)g_hbf)[i] = o;
        return;
    }
    b -= NC_BLK;
    int which = (b < NW_BLK) ? 0 : 1;
    if (which) b -= NW_BLK;
    int i = b * 256 + t;
    if (i >= NW_ELEM) return;
    const float* W  = which ? W2  : W1;
    const float* Ws = which ? W2s : W1s;
    const float4* src = (i < 8 * F * F / 4) ? ((const float4*)W + i)
                                            : ((const float4*)Ws + (i - 8 * F * F / 4));
    float4 v = *src;
    __nv_bfloat162 p0 = __floats2bfloat162_rn(v.x, v.y);
    __nv_bfloat162 p1 = __floats2bfloat162_rn(v.z, v.w);
    uint2 o; o.x = *(unsigned*)&p0; o.y = *(unsigned*)&p1;
    int row = i >> 5, c4 = i & 31;
    ((uint2*)(which == 0 ? g_Wb1 : g_Wb2))[(size_t)row * ROW2W + c4] = o;
}

// ---------------- launch 2: single-kernel scan (fence-and-flag, 98 resident blocks) ----------------
#define SCAN_BLK 98

__global__ void __launch_bounds__(1024) k_scan() {
    __shared__ int ws[32];
    __shared__ int s_last;
    int b = blockIdx.x, t = threadIdx.x;
    int lane = t & 31, wid = t >> 5;
    int base = b * 4096 + t * 4;
    int4 v4 = make_int4(0, 0, 0, 0);
    if (base + 3 < NKEY) v4 = *(const int4*)&g_deg2[base];
    else if (base < NKEY) {
        v4.x = g_deg2[base];
        if (base + 1 < NKEY) v4.y = g_deg2[base + 1];
        if (base + 2 < NKEY) v4.z = g_deg2[base + 2];
    }
    int s = v4.x + v4.y + v4.z + v4.w;
    int x = s;
    #pragma unroll
    for (int o = 1; o < 32; o <<= 1) { int u = __shfl_up_sync(~0u, x, o); if (lane >= o) x += u; }
    if (lane == 31) ws[wid] = x;
    __syncthreads();
    if (wid == 0) {
        int w = ws[lane];
        #pragma unroll
        for (int o = 1; o < 32; o <<= 1) { int u = __shfl_up_sync(~0u, w, o); if (lane >= o) w += u; }
        ws[lane] = w;
    }
    __syncthreads();
    int blk_excl = (x - s) + (wid > 0 ? ws[wid - 1] : 0);
    int blk_total = ws[31];
    __syncthreads();
    if (t == 0) {
        g_bsum[b] = blk_total;
        __threadfence();
        int tk = atomicAdd(&g_tick, 1);
        s_last = (tk == SCAN_BLK - 1) ? 1 : 0;
    }
    __syncthreads();
    if (s_last && wid == 0) {
        int v[4]; int psum = 0;
        #pragma unroll
        for (int j = 0; j < 4; j++) {
            int k = lane * 4 + j;
            v[j] = (k < SCAN_BLK) ? g_bsum[k] : 0;
            psum += v[j];
        }
        int xx = psum;
        #pragma unroll
        for (int o = 1; o < 32; o <<= 1) { int u = __shfl_up_sync(~0u, xx, o); if (lane >= o) xx += u; }
        int run = xx - psum;
        #pragma unroll
        for (int j = 0; j < 4; j++) {
            int k = lane * 4 + j;
            if (k < SCAN_BLK) g_boff[k] = run;
            run += v[j];
        }
        if (lane == 31) g_off2[NKEY] = run;
        __syncwarp();
        if (lane == 0) { __threadfence(); g_flag = 1; }
    }
    if (t == 0) { while (g_flag == 0) __nanosleep(64); }
    __syncthreads();
    __threadfence();
    int bb = g_boff[b] + blk_excl;
    int e0 = bb;
    int e1 = e0 + v4.x;
    int e2 = e1 + v4.y;
    int e3 = e2 + v4.z;
    if (base + 3 < NKEY) {
        *(int4*)&g_off2[base] = make_int4(e0, e1, e2, e3);
        *(int4*)&g_cur2[base] = make_int4(e0, e1, e2, e3);
    } else if (base < NKEY) {
        g_off2[base] = e0; g_cur2[base] = e0;
        if (base + 1 < NKEY) { g_off2[base + 1] = e1; g_cur2[base + 1] = e1; }
        if (base + 2 < NKEY) { g_off2[base + 2] = e2; g_cur2[base + 2] = e2; }
    }
}

// ---------------- launch 3: scatter (+ reset scan flags) ----------------
__global__ void k_scatter(const int* __restrict__ src, const int* __restrict__ dst,
                          const int* __restrict__ et) {
    if (blockIdx.x == 0 && threadIdx.x == 0) { g_tick = 0; g_flag = 0; }
    int e = blockIdx.x * blockDim.x + threadIdx.x;
    if (e < NE) {
        int d = dst[e];
        int p = atomicAdd(&g_cur2[et[e] * NN + d], 1);
        g_epack[p] = (uint32_t)src[e] | ((uint32_t)d << 16);
    }
}

// ---------------- launch 4/5: fused gather + GEMM + epilogue ----------------
// 64-row CTA, 256 threads: warps 0-3 consumers (wmma), warps 4-7 producers (gather).
// __launch_bounds__(256, 2): cap regs at 128 so TWO CTAs co-reside per SM.
__global__ void __launch_bounds__(256, 2)
k_fused(const float* __restrict__ bias, int layer) {
    extern __shared__ char smraw[];
    uint32_t sbase = (uint32_t)__cvta_generic_to_shared(smraw);
    const __nv_bfloat16* hinp = layer ? g_h1 : g_hbf;
    const uint2* hin4 = (const uint2*)hinp;       // dense: 32 uint2 per row
    const __nv_bfloat16* Wb = layer ? g_Wb2 : g_Wb1;
    int m0 = blockIdx.x * MROWS;
    int t = threadIdx.x;
    int warp = t >> 5, lane = t & 31;
    uint32_t mbF0 = sbase + 2 * STAGEB;           // full[0], full[1]
    uint32_t mbE0 = mbF0 + 16;                    // empty[0], empty[1]

    if (t == 0) {
        mbar_init(mbF0, 129);     mbar_init(mbF0 + 8, 129);   // 128 producer thr + expect_tx
        mbar_init(mbE0, 128);     mbar_init(mbE0 + 8, 128);   // 128 consumer thr
    }
    __syncthreads();

    if (warp < 4) {
        // ---------------- consumer: warp tile 32x64 ----------------
        int wm = warp >> 1;      // 0..1 (32-row tiles)
        int wn = warp & 1;       // 0..1 (64-col tiles)
        wmma::fragment<wmma::accumulator, 16, 16, 16, float> c[2][4];
        #pragma unroll
        for (int i = 0; i < 2; i++)
            #pragma unroll
            for (int j = 0; j < 4; j++) wmma::fill_fragment(c[i][j], 0.f);

        for (int kb = 0; kb < 9; kb++) {
            int s = kb & 1;
            uint32_t par = (kb >> 1) & 1;
            mbar_wait(mbF0 + 8 * s, par);
            const __nv_bfloat16* sA = (const __nv_bfloat16*)(smraw + s * STAGEB);
            const __nv_bfloat16* sB = (const __nv_bfloat16*)(smraw + s * STAGEB + TILEA);
            #pragma unroll
            for (int ks = 0; ks < 8; ks++) {
                wmma::fragment<wmma::matrix_a, 16, 16, 16, __nv_bfloat16, wmma::row_major> af[2];
                #pragma unroll
                for (int i = 0; i < 2; i++)
                    wmma::load_matrix_sync(af[i], sA + (wm * 32 + i * 16) * PADC + ks * 16, PADC);
                #pragma unroll
                for (int j = 0; j < 4; j++) {
                    wmma::fragment<wmma::matrix_b, 16, 16, 16, __nv_bfloat16, wmma::row_major> bf;
                    wmma::load_matrix_sync(bf, sB + (ks * 16) * PADC + wn * 64 + j * 16, PADC);
                    #pragma unroll
                    for (int i = 0; i < 2; i++)
                        wmma::mma_sync(c[i][j], af[i], bf, c[i][j]);
                }
            }
            mbar_arrive(mbE0 + 8 * s);
        }
        __syncthreads();
        float* sC = (float*)smraw;
        #pragma unroll
        for (int i = 0; i < 2; i++)
            #pragma unroll
            for (int j = 0; j < 4; j++)
                wmma::store_matrix_sync(sC + (wm * 32 + i * 16) * 132 + wn * 64 + j * 16,
                                        c[i][j], 132, wmma::mem_row_major);
    } else {
        // ---------------- producer ----------------
        int pw = warp - 4;                        // 0..3, owns rows pw*16..pw*16+15
        int nn = NN - m0; if (nn > MROWS) nn = MROWS;
        for (int kb = 0; kb < 9; kb++) {
            int s = kb & 1;
            uint32_t par = ((kb >> 1) & 1) ^ 1;
            mbar_wait(mbE0 + 8 * s, par);
            uint32_t mbF = mbF0 + 8 * s;
            char* sAp = smraw + s * STAGEB;
            if (t == 128) {
                mbar_arrive_expect_tx(mbF, TILEW);
                bulk_g2s(sbase + s * STAGEB + TILEA,
                         (const void*)(Wb + (size_t)kb * 128 * PADC), TILEW, mbF);
            }
            if (kb < 8) {
                #pragma unroll
                for (int r = 0; r < 16; r++)
                    *(uint2*)(sAp + (pw * 16 + r) * ROWB + lane * 8) = make_uint2(0u, 0u);
                int nbeg = pw * 16;
                int nend = nbeg + 16; if (nend > nn) nend = nn;
                if (nbeg < nend) {
                    int wb = g_off2[kb * NN + m0 + nbeg];
                    int we = g_off2[kb * NN + m0 + nend];
                    int cur = -1;
                    float a0 = 0.f, a1 = 0.f, a2 = 0.f, a3 = 0.f;
                    for (int e = wb; e < we; e += 32) {
                        uint32_t pk = 0xFFFF0000u;               // sentinel dst
                        if (e + lane < we) pk = g_epack[e + lane];
                        int ccnt = we - e; if (ccnt > 32) ccnt = 32;
                        for (int g = 0; g < ccnt; g += 4) {
                            uint2 rr[4]; int dd[4];
                            #pragma unroll
                            for (int j = 0; j < 4; j++) {
                                uint32_t p = __shfl_sync(0xffffffffu, pk, g + j);
                                dd[j] = (int)(p >> 16);
                                rr[j] = hin4[(size_t)(p & 0xFFFFu) * 32 + lane];
                            }
                            #pragma unroll
                            for (int j = 0; j < 4; j++) {
                                if (dd[j] == 0xFFFF) continue;
                                if (dd[j] != cur) {
                                    if (cur >= 0) {
                                        __nv_bfloat162 o0 = __floats2bfloat162_rn(a0, a1);
                                        __nv_bfloat162 o1 = __floats2bfloat162_rn(a2, a3);
                                        *(uint2*)(sAp + (cur - m0) * ROWB + lane * 8) =
                                            make_uint2(*(unsigned*)&o0, *(unsigned*)&o1);
                                    }
                                    cur = dd[j];
                                    a0 = a1 = a2 = a3 = 0.f;
                                }
                                __nv_bfloat162 p0 = *(__nv_bfloat162*)&rr[j].x;
                                __nv_bfloat162 p1 = *(__nv_bfloat162*)&rr[j].y;
                                float2 f0 = __bfloat1622float2(p0);
                                float2 f1 = __bfloat1622float2(p1);
                                a0 += f0.x; a1 += f0.y; a2 += f1.x; a3 += f1.y;
                            }
                        }
                    }
                    if (cur >= 0) {
                        __nv_bfloat162 o0 = __floats2bfloat162_rn(a0, a1);
                        __nv_bfloat162 o1 = __floats2bfloat162_rn(a2, a3);
                        *(uint2*)(sAp + (cur - m0) * ROWB + lane * 8) =
                            make_uint2(*(unsigned*)&o0, *(unsigned*)&o1);
                    }
                }
            } else {
                // self-loop stage: copy my 16 h rows into sA
                #pragma unroll
                for (int r = 0; r < 16; r++) {
                    int row = pw * 16 + r;
                    int gr = m0 + row;
                    uint2 v = (gr < NN) ? hin4[(size_t)gr * 32 + lane] : make_uint2(0u, 0u);
                    *(uint2*)(sAp + row * ROWB + lane * 8) = v;
                }
            }
            mbar_arrive(mbF);
        }
        __syncthreads();
    }
    __syncthreads();

    // ---------------- epilogue (all 256 threads), C is 64x132 fp32 ----------------
    float* sC = (float*)smraw;
    if (layer == 0) {
        #pragma unroll
        for (int i = 0; i < 8; i++) {
            int idx = t + i * 256;               // 0..2047
            int row = idx >> 5;
            int c4  = idx & 31;
            if (m0 + row < NN) {
                float* sp = sC + row * 132 + c4 * 4;
                float x = fmaxf(sp[0] + bias[c4 * 4 + 0], 0.f);
                float y = fmaxf(sp[1] + bias[c4 * 4 + 1], 0.f);
                float z = fmaxf(sp[2] + bias[c4 * 4 + 2], 0.f);
                float w = fmaxf(sp[3] + bias[c4 * 4 + 3], 0.f);
                __nv_bfloat162 p0 = __floats2bfloat162_rn(x, y);
                __nv_bfloat162 p1 = __floats2bfloat162_rn(z, w);
                uint2 o; o.x = *(unsigned*)&p0; o.y = *(unsigned*)&p1;
                ((uint2*)g_h1)[(size_t)(m0 + row) * 32 + c4] = o;
            }
        }
    } else {
        int col = t & 127;
        int rg = t >> 7;                         // 0..1
        float bc = bias[col];
        float s = 0.f;
        for (int r = rg * 32; r < rg * 32 + 32; r++) {
            if (m0 + r < NN) s += fmaxf(sC[r * 132 + col] + bc, 0.f);
        }
        atomicAdd(&g_pool[col], s);
        // re-zero g_deg2 for the next replay
        int gid = blockIdx.x * 256 + t;
        if (gid < NKEY / 2) ((int2*)g_deg2)[gid] = make_int2(0, 0);
    }
}

// ---------------- launch 6: final (+ re-zero pool) ----------------
__global__ void k_final(const float* __restrict__ fc_w, const float* __restrict__ fc_b,
                        float* __restrict__ out) {
    __shared__ float red[F];
    int t = threadIdx.x;
    red[t] = g_pool[t] * (1.f / (float)NN) * fc_w[t];
    __syncthreads();
    for (int o = 64; o > 0; o >>= 1) {
        if (t < o) red[t] += red[t + o];
        __syncthreads();
    }
    if (t == 0) {
        float logit = red[0] + fc_b[0];
        out[0] = 1.f / (1.f + expf(-logit));
    }
    g_pool[t] = 0.f;
}

// ---------------- launch ----------------
extern "C" void kernel_launch(void* const* d_in, const int* in_sizes, int n_in,
                              void* d_out, int out_size) {
    const float* in_feat = (const float*)d_in[0];
    const float* W1   = (const float*)d_in[1];
    const float* W1s  = (const float*)d_in[2];
    const float* b1   = (const float*)d_in[3];
    const float* W2   = (const float*)d_in[4];
    const float* W2s  = (const float*)d_in[5];
    const float* b2   = (const float*)d_in[6];
    const float* fcw  = (const float*)d_in[7];
    const float* fcb  = (const float*)d_in[8];
    const int*   src  = (const int*)d_in[9];
    const int*   dst  = (const int*)d_in[10];
    const int*   et   = (const int*)d_in[11];
    float* out = (float*)d_out;

    cudaFuncSetAttribute(k_fused, cudaFuncAttributeMaxDynamicSharedMemorySize, GEMM_SMEM);

    k_front<<<FRONT_GRID, 256>>>(in_feat, W1, W1s, W2, W2s, dst, et);   // 1
    k_scan<<<SCAN_BLK, 1024>>>();                                       // 2
    k_scatter<<<(NE + 255) / 256, 256>>>(src, dst, et);                 // 3
    k_fused<<<GRID, 256, GEMM_SMEM>>>(b1, 0);                           // 4  <- ncu target
    k_fused<<<GRID, 256, GEMM_SMEM>>>(b2, 1);                           // 5
    k_final<<<1, 128>>>(fcw, fcb, out);                                 // 6
}

// round 15
// speedup vs baseline: 1.5708x; 1.1276x over previous
#include <cuda_runtime.h>
#include <cuda_bf16.h>
#include <mma.h>
#include <math.h>
#include <cstdint>

using namespace nvcuda;

// Problem constants
#define NN 50000
#define NE 800000
#define F  128
#define R  8
#define NKEY (NN * R)                // 400000 (rel,dst) buckets, key = rel*NN + dst

// smem tile row: 136 bf16 = 272 bytes -> LDSM rows hit banks 4r mod 32 (conflict-free)
#define PADC 136
#define ROW2W 34                     // uint2 per padded weight row
#define ROWB (PADC * 2)              // 272 bytes
#define TILEB (128 * ROWB)           // 34816 bytes per 128-row tile
#define NSTAGE 3
#define STAGEB (2 * TILEB)           // A + B per stage = 69632
#define GEMM_SMEM (NSTAGE * STAGEB + 64)  // 208960 -> 1 CTA/SM

#define MROWS 128
#define GRID ((NN + MROWS - 1) / MROWS)   // 391

// ---------------- device scratch (no cudaMalloc allowed) ----------------
__device__ __nv_bfloat16 g_h1[(size_t)NN * F];
__device__ __nv_bfloat16 g_hbf[(size_t)NN * F];
__device__ __nv_bfloat16 g_Wb1[9 * 128 * PADC];   // W1 blocks (+self), padded rows
__device__ __nv_bfloat16 g_Wb2[9 * 128 * PADC];
__device__ int      g_deg2[NKEY];
__device__ int      g_off2[NKEY + 1];
__device__ int      g_cur2[NKEY];
__device__ int      g_bsum[128];
__device__ int      g_boff[128];
__device__ int      g_tick;
__device__ volatile int g_flag;
__device__ uint32_t g_epack[NE];                  // src | dst<<16, sorted by (rel,dst)
__device__ float    g_pool[F];

// ---------------- PTX helpers ----------------
__device__ __forceinline__ void mbar_init(uint32_t mbar, uint32_t cnt) {
    asm volatile("mbarrier.init.shared.b64 [%0], %1;" :: "r"(mbar), "r"(cnt) : "memory");
}
__device__ __forceinline__ void mbar_arrive(uint32_t mbar) {
    asm volatile("mbarrier.arrive.release.cta.shared::cta.b64 _, [%0];" :: "r"(mbar) : "memory");
}
__device__ __forceinline__ void mbar_arrive_expect_tx(uint32_t mbar, uint32_t bytes) {
    asm volatile("mbarrier.arrive.expect_tx.shared.b64 _, [%0], %1;"
                 :: "r"(mbar), "r"(bytes) : "memory");
}
__device__ __forceinline__ void mbar_wait(uint32_t mbar, uint32_t parity) {
    asm volatile(
        "{\n\t.reg .pred P;\n\t"
        "W%=:\n\t"
        "mbarrier.try_wait.parity.acquire.cta.shared::cta.b64 P, [%0], %1, 0x989680;\n\t"
        "@!P bra.uni W%=;\n\t}"
        :: "r"(mbar), "r"(parity) : "memory");
}
__device__ __forceinline__ void bulk_g2s(uint32_t sdst, const void* gsrc, uint32_t bytes,
                                         uint32_t mbar) {
    asm volatile(
        "cp.async.bulk.shared::cta.global.mbarrier::complete_tx::bytes [%0], [%1], %2, [%3];"
        :: "r"(sdst), "l"(gsrc), "r"(bytes), "r"(mbar) : "memory");
}

// ---------------- launch 1: hist + all fp32->bf16 converts ----------------
#define NH_BLK ((NE + 255) / 256)
#define NC_BLK ((NN * F / 4 + 255) / 256)
#define NW_ELEM (9 * F * F / 4)
#define NW_BLK ((NW_ELEM + 255) / 256)
#define FRONT_GRID (NH_BLK + NC_BLK + 2 * NW_BLK)

__global__ void __launch_bounds__(256)
k_front(const float* __restrict__ in_feat,
        const float* __restrict__ W1, const float* __restrict__ W1s,
        const float* __restrict__ W2, const float* __restrict__ W2s,
        const int* __restrict__ dst, const int* __restrict__ et) {
    int b = blockIdx.x;
    int t = threadIdx.x;
    if (b < NH_BLK) {
        int e = b * 256 + t;
        if (e < NE) atomicAdd(&g_deg2[et[e] * NN + dst[e]], 1);
        return;
    }
    b -= NH_BLK;
    if (b < NC_BLK) {
        int i = b * 256 + t;
        if (i >= NN * F / 4) return;
        float4 v = ((const float4*)in_feat)[i];
        __nv_bfloat162 p0 = __floats2bfloat162_rn(v.x, v.y);
        __nv_bfloat162 p1 = __floats2bfloat162_rn(v.z, v.w);
        uint2 o; o.x = *(unsigned*)&p0; o.y = *(unsigned*)&p1;
        ((uint2*)g_hbf)[i] = o;
        return;
    }
    b -= NC_BLK;
    int which = (b < NW_BLK) ? 0 : 1;
    if (which) b -= NW_BLK;
    int i = b * 256 + t;
    if (i >= NW_ELEM) return;
    const float* W  = which ? W2  : W1;
    const float* Ws = which ? W2s : W1s;
    const float4* src = (i < 8 * F * F / 4) ? ((const float4*)W + i)
                                            : ((const float4*)Ws + (i - 8 * F * F / 4));
    float4 v = *src;
    __nv_bfloat162 p0 = __floats2bfloat162_rn(v.x, v.y);
    __nv_bfloat162 p1 = __floats2bfloat162_rn(v.z, v.w);
    uint2 o; o.x = *(unsigned*)&p0; o.y = *(unsigned*)&p1;
    int row = i >> 5, c4 = i & 31;
    ((uint2*)(which == 0 ? g_Wb1 : g_Wb2))[(size_t)row * ROW2W + c4] = o;
}

// ---------------- launch 2: single-kernel scan (fence-and-flag, 98 resident blocks) ----------------
#define SCAN_BLK 98

__global__ void __launch_bounds__(1024) k_scan() {
    __shared__ int ws[32];
    __shared__ int s_last;
    int b = blockIdx.x, t = threadIdx.x;
    int lane = t & 31, wid = t >> 5;
    int base = b * 4096 + t * 4;
    int4 v4 = make_int4(0, 0, 0, 0);
    if (base + 3 < NKEY) v4 = *(const int4*)&g_deg2[base];
    else if (base < NKEY) {
        v4.x = g_deg2[base];
        if (base + 1 < NKEY) v4.y = g_deg2[base + 1];
        if (base + 2 < NKEY) v4.z = g_deg2[base + 2];
    }
    int s = v4.x + v4.y + v4.z + v4.w;
    int x = s;
    #pragma unroll
    for (int o = 1; o < 32; o <<= 1) { int u = __shfl_up_sync(~0u, x, o); if (lane >= o) x += u; }
    if (lane == 31) ws[wid] = x;
    __syncthreads();
    if (wid == 0) {
        int w = ws[lane];
        #pragma unroll
        for (int o = 1; o < 32; o <<= 1) { int u = __shfl_up_sync(~0u, w, o); if (lane >= o) w += u; }
        ws[lane] = w;
    }
    __syncthreads();
    int blk_excl = (x - s) + (wid > 0 ? ws[wid - 1] : 0);
    int blk_total = ws[31];
    __syncthreads();
    if (t == 0) {
        g_bsum[b] = blk_total;
        __threadfence();
        int tk = atomicAdd(&g_tick, 1);
        s_last = (tk == SCAN_BLK - 1) ? 1 : 0;
    }
    __syncthreads();
    if (s_last && wid == 0) {
        int v[4]; int psum = 0;
        #pragma unroll
        for (int j = 0; j < 4; j++) {
            int k = lane * 4 + j;
            v[j] = (k < SCAN_BLK) ? g_bsum[k] : 0;
            psum += v[j];
        }
        int xx = psum;
        #pragma unroll
        for (int o = 1; o < 32; o <<= 1) { int u = __shfl_up_sync(~0u, xx, o); if (lane >= o) xx += u; }
        int run = xx - psum;
        #pragma unroll
        for (int j = 0; j < 4; j++) {
            int k = lane * 4 + j;
            if (k < SCAN_BLK) g_boff[k] = run;
            run += v[j];
        }
        if (lane == 31) g_off2[NKEY] = run;
        __syncwarp();
        if (lane == 0) { __threadfence(); g_flag = 1; }
    }
    if (t == 0) { while (g_flag == 0) __nanosleep(64); }
    __syncthreads();
    __threadfence();
    int bb = g_boff[b] + blk_excl;
    int e0 = bb;
    int e1 = e0 + v4.x;
    int e2 = e1 + v4.y;
    int e3 = e2 + v4.z;
    if (base + 3 < NKEY) {
        *(int4*)&g_off2[base] = make_int4(e0, e1, e2, e3);
        *(int4*)&g_cur2[base] = make_int4(e0, e1, e2, e3);
    } else if (base < NKEY) {
        g_off2[base] = e0; g_cur2[base] = e0;
        if (base + 1 < NKEY) { g_off2[base + 1] = e1; g_cur2[base + 1] = e1; }
        if (base + 2 < NKEY) { g_off2[base + 2] = e2; g_cur2[base + 2] = e2; }
    }
}

// ---------------- launch 3: scatter (+ reset scan flags) ----------------
__global__ void k_scatter(const int* __restrict__ src, const int* __restrict__ dst,
                          const int* __restrict__ et) {
    if (blockIdx.x == 0 && threadIdx.x == 0) { g_tick = 0; g_flag = 0; }
    int e = blockIdx.x * blockDim.x + threadIdx.x;
    if (e < NE) {
        int d = dst[e];
        int p = atomicAdd(&g_cur2[et[e] * NN + d], 1);
        g_epack[p] = (uint32_t)src[e] | ((uint32_t)d << 16);
    }
}

// ---------------- launch 4/5: fused gather + GEMM + epilogue (warp-specialized) ----------------
// 512 threads: warps 0-7 consumers (wmma), warps 8-15 producers (gather).
// 3-stage pipeline; lane0-per-warp barrier arrivals (full cnt=9, empty cnt=8).
__global__ void __launch_bounds__(512)
k_fused(const float* __restrict__ bias, int layer) {
    extern __shared__ char smraw[];
    uint32_t sbase = (uint32_t)__cvta_generic_to_shared(smraw);
    const __nv_bfloat16* hinp = layer ? g_h1 : g_hbf;
    const uint2* hin4 = (const uint2*)hinp;       // dense: 32 uint2 per row
    const __nv_bfloat16* Wb = layer ? g_Wb2 : g_Wb1;
    int m0 = blockIdx.x * MROWS;
    int t = threadIdx.x;
    int warp = t >> 5, lane = t & 31;
    uint32_t mbF0 = sbase + NSTAGE * STAGEB;      // full[0..2]
    uint32_t mbE0 = mbF0 + 8 * NSTAGE;            // empty[0..2]

    if (t == 0) {
        #pragma unroll
        for (int s = 0; s < NSTAGE; s++) {
            mbar_init(mbF0 + 8 * s, 9);           // 8 producer warp-arrivals + 1 expect_tx
            mbar_init(mbE0 + 8 * s, 8);           // 8 consumer warp-arrivals
        }
    }
    __syncthreads();

    if (warp < 8) {
        // ---------------- consumer: warp tile 64x32 ----------------
        int wm = warp >> 2;      // 0..1 (64-row tiles)
        int wn = warp & 3;       // 0..3 (32-col tiles)
        wmma::fragment<wmma::accumulator, 16, 16, 16, float> c[4][2];
        #pragma unroll
        for (int i = 0; i < 4; i++)
            #pragma unroll
            for (int j = 0; j < 2; j++) wmma::fill_fragment(c[i][j], 0.f);

        for (int kb = 0; kb < 9; kb++) {
            int s = kb % NSTAGE;
            uint32_t par = (kb / NSTAGE) & 1;
            mbar_wait(mbF0 + 8 * s, par);
            const __nv_bfloat16* sA = (const __nv_bfloat16*)(smraw + s * STAGEB);
            const __nv_bfloat16* sB = sA + 128 * PADC;
            #pragma unroll
            for (int ks = 0; ks < 8; ks++) {
                wmma::fragment<wmma::matrix_b, 16, 16, 16, __nv_bfloat16, wmma::row_major> bf[2];
                #pragma unroll
                for (int j = 0; j < 2; j++)
                    wmma::load_matrix_sync(bf[j], sB + (ks * 16) * PADC + wn * 32 + j * 16, PADC);
                #pragma unroll
                for (int i = 0; i < 4; i++) {
                    wmma::fragment<wmma::matrix_a, 16, 16, 16, __nv_bfloat16, wmma::row_major> af;
                    wmma::load_matrix_sync(af, sA + (wm * 64 + i * 16) * PADC + ks * 16, PADC);
                    #pragma unroll
                    for (int j = 0; j < 2; j++)
                        wmma::mma_sync(c[i][j], af, bf[j], c[i][j]);
                }
            }
            __syncwarp();
            if (lane == 0) mbar_arrive(mbE0 + 8 * s);
        }
        __syncthreads();
        float* sC = (float*)smraw;
        #pragma unroll
        for (int i = 0; i < 4; i++)
            #pragma unroll
            for (int j = 0; j < 2; j++)
                wmma::store_matrix_sync(sC + (wm * 64 + i * 16) * 132 + wn * 32 + j * 16,
                                        c[i][j], 132, wmma::mem_row_major);
    } else {
        // ---------------- producer ----------------
        int pw = warp - 8;                        // 0..7, owns rows pw*16..pw*16+15
        int nn = NN - m0; if (nn > MROWS) nn = MROWS;
        for (int kb = 0; kb < 9; kb++) {
            int s = kb % NSTAGE;
            uint32_t par = ((kb / NSTAGE) & 1) ^ 1;
            mbar_wait(mbE0 + 8 * s, par);
            uint32_t mbF = mbF0 + 8 * s;
            char* sAp = smraw + s * STAGEB;
            if (t == 256) {
                mbar_arrive_expect_tx(mbF, TILEB);
                bulk_g2s(sbase + s * STAGEB + TILEB,
                         (const void*)(Wb + (size_t)kb * 128 * PADC), TILEB, mbF);
            }
            if (kb < 8) {
                // zero my 16 rows (lane's 8-byte slot)
                #pragma unroll
                for (int r = 0; r < 16; r++)
                    *(uint2*)(sAp + (pw * 16 + r) * ROWB + lane * 8) = make_uint2(0u, 0u);
                int nbeg = pw * 16;
                int nend = nbeg + 16; if (nend > nn) nend = nn;
                if (nbeg < nend) {
                    int wb = g_off2[kb * NN + m0 + nbeg];
                    int we = g_off2[kb * NN + m0 + nend];
                    int cur = -1;
                    float a0 = 0.f, a1 = 0.f, a2 = 0.f, a3 = 0.f;
                    for (int e = wb; e < we; e += 32) {
                        uint32_t pk = 0xFFFF0000u;               // sentinel dst
                        if (e + lane < we) pk = g_epack[e + lane];
                        int ccnt = we - e; if (ccnt > 32) ccnt = 32;
                        for (int g = 0; g < ccnt; g += 8) {
                            uint2 rr[8]; int dd[8];
                            #pragma unroll
                            for (int j = 0; j < 8; j++) {
                                uint32_t p = __shfl_sync(0xffffffffu, pk, g + j);
                                dd[j] = (int)(p >> 16);
                                rr[j] = hin4[(size_t)(p & 0xFFFFu) * 32 + lane];
                            }
                            #pragma unroll
                            for (int j = 0; j < 8; j++) {
                                if (dd[j] == 0xFFFF) continue;
                                if (dd[j] != cur) {
                                    if (cur >= 0) {
                                        __nv_bfloat162 o0 = __floats2bfloat162_rn(a0, a1);
                                        __nv_bfloat162 o1 = __floats2bfloat162_rn(a2, a3);
                                        *(uint2*)(sAp + (cur - m0) * ROWB + lane * 8) =
                                            make_uint2(*(unsigned*)&o0, *(unsigned*)&o1);
                                    }
                                    cur = dd[j];
                                    a0 = a1 = a2 = a3 = 0.f;
                                }
                                __nv_bfloat162 p0 = *(__nv_bfloat162*)&rr[j].x;
                                __nv_bfloat162 p1 = *(__nv_bfloat162*)&rr[j].y;
                                float2 f0 = __bfloat1622float2(p0);
                                float2 f1 = __bfloat1622float2(p1);
                                a0 += f0.x; a1 += f0.y; a2 += f1.x; a3 += f1.y;
                            }
                        }
                    }
                    if (cur >= 0) {
                        __nv_bfloat162 o0 = __floats2bfloat162_rn(a0, a1);
                        __nv_bfloat162 o1 = __floats2bfloat162_rn(a2, a3);
                        *(uint2*)(sAp + (cur - m0) * ROWB + lane * 8) =
                            make_uint2(*(unsigned*)&o0, *(unsigned*)&o1);
                    }
                }
            } else {
                // self-loop stage: copy my 16 h rows into sA
                #pragma unroll
                for (int r = 0; r < 16; r++) {
                    int row = pw * 16 + r;
                    int gr = m0 + row;
                    uint2 v = (gr < NN) ? hin4[(size_t)gr * 32 + lane] : make_uint2(0u, 0u);
                    *(uint2*)(sAp + row * ROWB + lane * 8) = v;
                }
            }
            __syncwarp();
            if (lane == 0) mbar_arrive(mbF);
        }
        __syncthreads();
    }
    __syncthreads();

    // ---------------- epilogue (all 512 threads), C is 128x132 fp32 ----------------
    float* sC = (float*)smraw;
    if (layer == 0) {
        #pragma unroll
        for (int i = 0; i < 8; i++) {
            int idx = t + i * 512;
            int row = idx >> 5;
            int c4  = idx & 31;
            if (m0 + row < NN) {
                float* sp = sC + row * 132 + c4 * 4;
                float x = fmaxf(sp[0] + bias[c4 * 4 + 0], 0.f);
                float y = fmaxf(sp[1] + bias[c4 * 4 + 1], 0.f);
                float z = fmaxf(sp[2] + bias[c4 * 4 + 2], 0.f);
                float w = fmaxf(sp[3] + bias[c4 * 4 + 3], 0.f);
                __nv_bfloat162 p0 = __floats2bfloat162_rn(x, y);
                __nv_bfloat162 p1 = __floats2bfloat162_rn(z, w);
                uint2 o; o.x = *(unsigned*)&p0; o.y = *(unsigned*)&p1;
                ((uint2*)g_h1)[(size_t)(m0 + row) * 32 + c4] = o;
            }
        }
    } else {
        int col = t & 127;
        int rg = t >> 7;                          // 0..3
        float bc = bias[col];
        float s = 0.f;
        for (int r = rg * 32; r < rg * 32 + 32; r++) {
            if (m0 + r < NN) s += fmaxf(sC[r * 132 + col] + bc, 0.f);
        }
        atomicAdd(&g_pool[col], s);
        // re-zero g_deg2 for the next replay
        int gid = blockIdx.x * 512 + t;
        if (gid < NKEY / 2) ((int2*)g_deg2)[gid] = make_int2(0, 0);
    }
}

// ---------------- launch 6: final (+ re-zero pool) ----------------
__global__ void k_final(const float* __restrict__ fc_w, const float* __restrict__ fc_b,
                        float* __restrict__ out) {
    __shared__ float red[F];
    int t = threadIdx.x;
    red[t] = g_pool[t] * (1.f / (float)NN) * fc_w[t];
    __syncthreads();
    for (int o = 64; o > 0; o >>= 1) {
        if (t < o) red[t] += red[t + o];
        __syncthreads();
    }
    if (t == 0) {
        float logit = red[0] + fc_b[0];
        out[0] = 1.f / (1.f + expf(-logit));
    }
    g_pool[t] = 0.f;
}

// ---------------- launch ----------------
extern "C" void kernel_launch(void* const* d_in, const int* in_sizes, int n_in,
                              void* d_out, int out_size) {
    const float* in_feat = (const float*)d_in[0];
    const float* W1   = (const float*)d_in[1];
    const float* W1s  = (const float*)d_in[2];
    const float* b1   = (const float*)d_in[3];
    const float* W2   = (const float*)d_in[4];
    const float* W2s  = (const float*)d_in[5];
    const float* b2   = (const float*)d_in[6];
    const float* fcw  = (const float*)d_in[7];
    const float* fcb  = (const float*)d_in[8];
    const int*   src  = (const int*)d_in[9];
    const int*   dst  = (const int*)d_in[10];
    const int*   et   = (const int*)d_in[11];
    float* out = (float*)d_out;

    cudaFuncSetAttribute(k_fused, cudaFuncAttributeMaxDynamicSharedMemorySize, GEMM_SMEM);

    k_front<<<FRONT_GRID, 256>>>(in_feat, W1, W1s, W2, W2s, dst, et);   // 1
    k_scan<<<SCAN_BLK, 1024>>>();                                       // 2
    k_scatter<<<(NE + 255) / 256, 256>>>(src, dst, et);                 // 3
    k_fused<<<GRID, 512, GEMM_SMEM>>>(b1, 0);                           // 4  <- ncu target
    k_fused<<<GRID, 512, GEMM_SMEM>>>(b2, 1);                           // 5
    k_final<<<1, 128>>>(fcw, fcb, out);                                 // 6
}